// round 2
// baseline (speedup 1.0000x reference)
#include <cuda_runtime.h>
#include <cuda_bf16.h>
#include <cstdint>

// Problem constants
#define NN 100000
#define EE 1600000
#define NF 128
#define EF 32
#define HID 64
#define NLAYERS 3
#define NGRAPH 512

// ---------------- scratch buffers (device globals; no allocation) ----------------
__device__ float g_h[NN * HID];
__device__ float g_agg[NN * HID];
__device__ float g_t1[NN * 2 * HID];
__device__ float g_t2[NN * HID];
__device__ float g_st1[2 * 128];   // sum[128], sumsq[128]
__device__ float g_st2[2 * 64];    // sum[64],  sumsq[64]
__device__ float g_sc1[128], g_sh1[128];
__device__ float g_sc2[64],  g_sh2[64];
__device__ float g_pool[NGRAPH * HID];
__device__ float g_cnt[NGRAPH];
__device__ int   g_idx64;          // 1 if edge_index/batch are int64

// ---------------- f32x2 packed helpers (Blackwell) ----------------
__device__ __forceinline__ unsigned long long f2pack(float x, float y) {
    unsigned long long r;
    asm("mov.b64 %0, {%1, %2};" : "=l"(r) : "f"(x), "f"(y));
    return r;
}
__device__ __forceinline__ void f2unpack(unsigned long long v, float& x, float& y) {
    asm("mov.b64 {%0, %1}, %2;" : "=f"(x), "=f"(y) : "l"(v));
}
__device__ __forceinline__ unsigned long long ffma2(unsigned long long a, unsigned long long b,
                                                    unsigned long long c) {
    unsigned long long d;
    asm("fma.rn.f32x2 %0, %1, %2, %3;" : "=l"(d) : "l"(a), "l"(b), "l"(c));
    return d;
}

__device__ __forceinline__ void red_add_v4(float* p, float4 v) {
    asm volatile("red.global.add.v4.f32 [%0], {%1,%2,%3,%4};"
                 :: "l"(p), "f"(v.x), "f"(v.y), "f"(v.z), "f"(v.w) : "memory");
}
__device__ __forceinline__ void red_add_v2(float* p, float2 v) {
    asm volatile("red.global.add.v2.f32 [%0], {%1,%2};"
                 :: "l"(p), "f"(v.x), "f"(v.y) : "memory");
}

// ---------------- dtype probe: int64 edge_index has all-zero odd int32 words ----
__global__ void detect_kernel(const int* __restrict__ ei) {
    if (threadIdx.x == 0 && blockIdx.x == 0) {
        int nz = 0;
        for (int k = 0; k < 1024; ++k) nz |= ei[2 * k + 1];
        g_idx64 = (nz == 0) ? 1 : 0;
    }
}

// ---------------- zero kernel ----------------
__global__ void zero_kernel(float4* __restrict__ p, int n4) {
    int i = blockIdx.x * blockDim.x + threadIdx.x;
    if (i < n4) p[i] = make_float4(0.f, 0.f, 0.f, 0.f);
}

// ---------------- generic tiled GEMM with fused prologue/epilogue ----------------
// C[M,NC] = Aop(A)[M,K] @ B[K,NC] + bias
// AMODE 0: Aop = A0
// AMODE 1: Aop = (1+eps)*A0 + A1
// AMODE 2: Aop = relu(A0*sc[k] + sh[k])  (BN1+relu applied on the fly)
// STATS:   accumulate per-column sum/sumsq of C into stats[0..NC) / stats[NC..2NC)
template <int K, int NC, int AMODE, bool STATS>
__global__ __launch_bounds__(256) void gemm_kernel(
    const float* __restrict__ A0, const float* __restrict__ A1,
    const float* __restrict__ B, const float* __restrict__ bias,
    float* __restrict__ C, float* __restrict__ stats,
    const float* __restrict__ sc, const float* __restrict__ sh,
    const float* __restrict__ epsp, int M)
{
    constexpr int BM = 64, BK = 32;
    constexpr int TN  = NC / 16;   // 4 or 8 cols per thread
    constexpr int TN2 = TN / 2;

    __shared__ float As[BM][36];
    __shared__ float Bs[BK][NC];
    __shared__ float scs[K], shs[K];
    __shared__ float ssum[NC], ssq[NC];

    const int tid = threadIdx.x;
    const int tx = tid & 15, ty = tid >> 4;
    const int r0 = blockIdx.x * BM;

    float epsv = 0.f;
    if (AMODE == 1) epsv = 1.0f + *epsp;
    if (AMODE == 2) {
        for (int i = tid; i < K; i += 256) { scs[i] = sc[i]; shs[i] = sh[i]; }
    }
    if (STATS) {
        for (int i = tid; i < NC; i += 256) { ssum[i] = 0.f; ssq[i] = 0.f; }
    }
    if (AMODE == 2 || STATS) __syncthreads();   // FIX: scs/shs must be visible before A-tile load

    unsigned long long acc[4][TN2];
#pragma unroll
    for (int i = 0; i < 4; ++i)
#pragma unroll
        for (int j = 0; j < TN2; ++j) acc[i][j] = 0ULL;

    for (int k0 = 0; k0 < K; k0 += BK) {
        // ---- load A tile (64 x 32) : 512 float4, 2 per thread ----
#pragma unroll
        for (int l = 0; l < 2; ++l) {
            int idx = tid + l * 256;
            int row = idx >> 3;
            int q   = idx & 7;
            int grow = r0 + row;
            float4 v = make_float4(0.f, 0.f, 0.f, 0.f);
            if (grow < M) {
                int gk = k0 + q * 4;
                if (AMODE == 0) {
                    v = *(const float4*)&A0[(size_t)grow * K + gk];
                } else if (AMODE == 1) {
                    float4 hv = *(const float4*)&A0[(size_t)grow * K + gk];
                    float4 av = *(const float4*)&A1[(size_t)grow * K + gk];
                    v.x = fmaf(epsv, hv.x, av.x);
                    v.y = fmaf(epsv, hv.y, av.y);
                    v.z = fmaf(epsv, hv.z, av.z);
                    v.w = fmaf(epsv, hv.w, av.w);
                } else {
                    float4 tv = *(const float4*)&A0[(size_t)grow * K + gk];
                    v.x = fmaxf(fmaf(tv.x, scs[gk + 0], shs[gk + 0]), 0.f);
                    v.y = fmaxf(fmaf(tv.y, scs[gk + 1], shs[gk + 1]), 0.f);
                    v.z = fmaxf(fmaf(tv.z, scs[gk + 2], shs[gk + 2]), 0.f);
                    v.w = fmaxf(fmaf(tv.w, scs[gk + 3], shs[gk + 3]), 0.f);
                }
            }
            *(float4*)&As[row][q * 4] = v;
        }
        // ---- load B tile (32 x NC) ----
        constexpr int BLD = (BK * NC / 4) / 256;
#pragma unroll
        for (int l = 0; l < BLD; ++l) {
            int idx = tid + l * 256;
            int kk = idx / (NC / 4);
            int c  = (idx % (NC / 4)) * 4;
            *(float4*)&Bs[kk][c] = *(const float4*)&B[(size_t)(k0 + kk) * NC + c];
        }
        __syncthreads();
#pragma unroll
        for (int kk = 0; kk < BK; ++kk) {
            unsigned long long bp[TN2];
            const unsigned long long* bsrc =
                reinterpret_cast<const unsigned long long*>(&Bs[kk][tx * TN]);
#pragma unroll
            for (int j = 0; j < TN2; ++j) bp[j] = bsrc[j];
#pragma unroll
            for (int i = 0; i < 4; ++i) {
                float a = As[ty * 4 + i][kk];
                unsigned long long ap = f2pack(a, a);
#pragma unroll
                for (int j = 0; j < TN2; ++j) acc[i][j] = ffma2(ap, bp[j], acc[i][j]);
            }
        }
        __syncthreads();
    }

    // ---- epilogue ----
    float bcol[TN];
#pragma unroll
    for (int j = 0; j < TN; ++j) bcol[j] = bias[tx * TN + j];

    float csum[TN], csq[TN];
#pragma unroll
    for (int j = 0; j < TN; ++j) { csum[j] = 0.f; csq[j] = 0.f; }

#pragma unroll
    for (int i = 0; i < 4; ++i) {
        int row = r0 + ty * 4 + i;
        if (row < M) {
            float o[TN];
#pragma unroll
            for (int j = 0; j < TN2; ++j) f2unpack(acc[i][j], o[2 * j], o[2 * j + 1]);
#pragma unroll
            for (int j = 0; j < TN; ++j) o[j] += bcol[j];
#pragma unroll
            for (int j4 = 0; j4 < TN; j4 += 4)
                *(float4*)&C[(size_t)row * NC + tx * TN + j4] =
                    make_float4(o[j4], o[j4 + 1], o[j4 + 2], o[j4 + 3]);
            if (STATS) {
#pragma unroll
                for (int j = 0; j < TN; ++j) { csum[j] += o[j]; csq[j] += o[j] * o[j]; }
            }
        }
    }
    if (STATS) {
#pragma unroll
        for (int j = 0; j < TN; ++j) {
            atomicAdd(&ssum[tx * TN + j], csum[j]);
            atomicAdd(&ssq[tx * TN + j], csq[j]);
        }
        __syncthreads();
        if (tid < NC) {
            atomicAdd(&stats[tid], ssum[tid]);
            atomicAdd(&stats[NC + tid], ssq[tid]);
        }
    }
}

// ---------------- BN finalize: scale/shift from sums ----------------
__global__ void bn_finalize(const float* __restrict__ stats, const float* __restrict__ g,
                            const float* __restrict__ b, float* __restrict__ sc,
                            float* __restrict__ sh, int NC, float invM)
{
    int i = threadIdx.x;
    if (i < NC) {
        float m = stats[i] * invM;
        float v = stats[NC + i] * invM - m * m;
        float rstd = rsqrtf(fmaxf(v, 0.f) + 1e-5f);
        float s = g[i] * rstd;
        sc[i] = s;
        sh[i] = b[i] - m * s;
    }
}

// ---------------- BN2 apply + relu (elementwise, 64 cols) ----------------
__global__ void bn_apply_relu(const float* __restrict__ t, float* __restrict__ h,
                              const float* __restrict__ sc, const float* __restrict__ sh,
                              int total4)
{
    int i = blockIdx.x * 256 + threadIdx.x;
    if (i < total4) {
        float4 v = ((const float4*)t)[i];
        int c = (i & 15) * 4;  // HID=64 -> 16 float4 groups per row
        float4 o;
        o.x = fmaxf(fmaf(v.x, sc[c + 0], sh[c + 0]), 0.f);
        o.y = fmaxf(fmaf(v.y, sc[c + 1], sh[c + 1]), 0.f);
        o.z = fmaxf(fmaf(v.z, sc[c + 2], sh[c + 2]), 0.f);
        o.w = fmaxf(fmaf(v.w, sc[c + 3], sh[c + 3]), 0.f);
        ((float4*)h)[i] = o;
    }
}

// ---------------- fused edge kernel ----------------
// per edge: proj = attr@W + eb ; msg = relu(h[src] + proj) ; agg[dst] += msg
__global__ __launch_bounds__(256) void edge_kernel(
    const float* __restrict__ attr, const int* __restrict__ eidx,
    const float* __restrict__ W, const float* __restrict__ eb,
    const float* __restrict__ h, float* __restrict__ agg)
{
    __shared__ float ws[32][64];
    __shared__ float att[128][36];
    __shared__ int   srcs[128], dsts[128];
    __shared__ float ebias[64];

    const int tid = threadIdx.x;
    const int e0 = blockIdx.x * 128;
    const int idx64 = g_idx64;

    // W (32x64 = 512 float4)
#pragma unroll
    for (int l = 0; l < 2; ++l) {
        int idx = tid + l * 256;
        ((float4*)&ws[0][0])[idx] = ((const float4*)W)[idx];
    }
    if (tid < 64) ebias[tid] = eb[tid];
    if (tid < 128) {
        if (idx64) {
            const long long* e64 = (const long long*)eidx;
            srcs[tid] = (int)e64[e0 + tid];
            dsts[tid] = (int)e64[EE + e0 + tid];
        } else {
            srcs[tid] = eidx[e0 + tid];
            dsts[tid] = eidx[EE + e0 + tid];
        }
    }
    // attr tile (128x32 = 1024 float4)
#pragma unroll
    for (int l = 0; l < 4; ++l) {
        int idx = tid + l * 256;
        int e = idx >> 3;
        int q = idx & 7;
        float4 v = *(const float4*)&attr[(size_t)(e0 + e) * EF + q * 4];
        *(float4*)&att[e][q * 4] = v;
    }
    __syncthreads();

    const int tx = tid & 7;    // col group: cols tx*8 .. tx*8+7
    const int ty = tid >> 3;   // edge group: edges ty*4 .. ty*4+3

    unsigned long long acc[4][4];
    unsigned long long bp0[4];
#pragma unroll
    for (int j = 0; j < 4; ++j)
        bp0[j] = f2pack(ebias[tx * 8 + 2 * j], ebias[tx * 8 + 2 * j + 1]);
#pragma unroll
    for (int i = 0; i < 4; ++i)
#pragma unroll
        for (int j = 0; j < 4; ++j) acc[i][j] = bp0[j];

#pragma unroll
    for (int kk = 0; kk < 32; ++kk) {
        const unsigned long long* wrow =
            reinterpret_cast<const unsigned long long*>(&ws[kk][tx * 8]);
        unsigned long long w0 = wrow[0], w1 = wrow[1], w2 = wrow[2], w3 = wrow[3];
#pragma unroll
        for (int i = 0; i < 4; ++i) {
            float a = att[ty * 4 + i][kk];
            unsigned long long ap = f2pack(a, a);
            acc[i][0] = ffma2(ap, w0, acc[i][0]);
            acc[i][1] = ffma2(ap, w1, acc[i][1]);
            acc[i][2] = ffma2(ap, w2, acc[i][2]);
            acc[i][3] = ffma2(ap, w3, acc[i][3]);
        }
    }

#pragma unroll
    for (int i = 0; i < 4; ++i) {
        int e = ty * 4 + i;
        int s = srcs[e], d = dsts[e];
        const float4* hp = (const float4*)&h[(size_t)s * HID + tx * 8];
        float4 h0 = hp[0], h1 = hp[1];
        float o[8];
        f2unpack(acc[i][0], o[0], o[1]);
        f2unpack(acc[i][1], o[2], o[3]);
        f2unpack(acc[i][2], o[4], o[5]);
        f2unpack(acc[i][3], o[6], o[7]);
        float4 m0 = make_float4(fmaxf(o[0] + h0.x, 0.f), fmaxf(o[1] + h0.y, 0.f),
                                fmaxf(o[2] + h0.z, 0.f), fmaxf(o[3] + h0.w, 0.f));
        float4 m1 = make_float4(fmaxf(o[4] + h1.x, 0.f), fmaxf(o[5] + h1.y, 0.f),
                                fmaxf(o[6] + h1.z, 0.f), fmaxf(o[7] + h1.w, 0.f));
        float* dp = &agg[(size_t)d * HID + tx * 8];
        red_add_v4(dp, m0);
        red_add_v4(dp + 4, m1);
    }
}

// ---------------- global mean pool ----------------
__global__ void pool_kernel(const float* __restrict__ h, const int* __restrict__ batch,
                            float* __restrict__ pool, float* __restrict__ cnt)
{
    int gid = blockIdx.x * 256 + threadIdx.x;  // NN*32 threads, float2 each
    if (gid >= NN * 32) return;
    int n = gid >> 5;
    int cp = gid & 31;
    int g = g_idx64 ? (int)((const long long*)batch)[n] : batch[n];
    float2 v = ((const float2*)h)[gid];
    red_add_v2(&pool[(size_t)g * HID + cp * 2], v);
    if (cp == 0) atomicAdd(&cnt[g], 1.0f);
}

__global__ void div_kernel(const float* __restrict__ pool, const float* __restrict__ cnt,
                           float* __restrict__ out)
{
    int i = blockIdx.x * 256 + threadIdx.x;
    if (i < NGRAPH * HID) {
        int g = i >> 6;
        out[i] = pool[i] / fmaxf(cnt[g], 1.0f);
    }
}

// ---------------- host launch ----------------
extern "C" void kernel_launch(void* const* d_in, const int* in_sizes, int n_in,
                              void* d_out, int out_size)
{
    const float* x     = (const float*)d_in[0];
    const int*   ei    = (const int*)d_in[1];
    const float* attr  = (const float*)d_in[2];
    const int*   batch = (const int*)d_in[3];
    const float* encW  = (const float*)d_in[4];
    const float* encb  = (const float*)d_in[5];
    const float* eps   = (const float*)d_in[6];
    const float* edgeW = (const float*)d_in[7];
    const float* edgeb = (const float*)d_in[8];
    const float* W1    = (const float*)d_in[9];
    const float* b1    = (const float*)d_in[10];
    const float* bn1g  = (const float*)d_in[11];
    const float* bn1b  = (const float*)d_in[12];
    const float* W2    = (const float*)d_in[13];
    const float* b2    = (const float*)d_in[14];
    const float* bn2g  = (const float*)d_in[15];
    const float* bn2b  = (const float*)d_in[16];
    float* out = (float*)d_out;

    float *h, *agg, *t1, *t2, *st1, *st2, *sc1, *sh1, *sc2, *sh2, *pool, *cnt;
    cudaGetSymbolAddress((void**)&h,   g_h);
    cudaGetSymbolAddress((void**)&agg, g_agg);
    cudaGetSymbolAddress((void**)&t1,  g_t1);
    cudaGetSymbolAddress((void**)&t2,  g_t2);
    cudaGetSymbolAddress((void**)&st1, g_st1);
    cudaGetSymbolAddress((void**)&st2, g_st2);
    cudaGetSymbolAddress((void**)&sc1, g_sc1);
    cudaGetSymbolAddress((void**)&sh1, g_sh1);
    cudaGetSymbolAddress((void**)&sc2, g_sc2);
    cudaGetSymbolAddress((void**)&sh2, g_sh2);
    cudaGetSymbolAddress((void**)&pool, g_pool);
    cudaGetSymbolAddress((void**)&cnt,  g_cnt);

    const int GB = (NN + 63) / 64;          // 1563 row tiles
    const float invM = 1.0f / (float)NN;

    detect_kernel<<<1, 32>>>(ei);

    // zero pool + counts
    zero_kernel<<<(NGRAPH * HID / 4 + 255) / 256, 256>>>((float4*)pool, NGRAPH * HID / 4);
    zero_kernel<<<1, 256>>>((float4*)cnt, NGRAPH / 4);

    // encoder: h = x @ encW + encb
    gemm_kernel<128, 64, 0, false><<<GB, 256>>>(x, nullptr, encW, encb, h,
                                                nullptr, nullptr, nullptr, nullptr, NN);

    for (int i = 0; i < NLAYERS; ++i) {
        zero_kernel<<<(NN * 16 + 255) / 256, 256>>>((float4*)agg, NN * 16);
        zero_kernel<<<1, 256>>>((float4*)st1, 64);
        zero_kernel<<<1, 256>>>((float4*)st2, 32);

        edge_kernel<<<EE / 128, 256>>>(attr, ei, edgeW + (size_t)i * EF * HID,
                                       edgeb + i * HID, h, agg);

        // t1 = ((1+eps)h + agg) @ W1 + b1, with BN1 stats
        gemm_kernel<64, 128, 1, true><<<GB, 256>>>(h, agg, W1 + (size_t)i * HID * 2 * HID,
                                                   b1 + i * 2 * HID, t1, st1,
                                                   nullptr, nullptr, eps + i, NN);
        bn_finalize<<<1, 128>>>(st1, bn1g + i * 128, bn1b + i * 128, sc1, sh1, 128, invM);

        // t2 = relu(bn1(t1)) @ W2 + b2, with BN2 stats
        gemm_kernel<128, 64, 2, true><<<GB, 256>>>(t1, nullptr, W2 + (size_t)i * 2 * HID * HID,
                                                   b2 + i * HID, t2, st2,
                                                   sc1, sh1, nullptr, NN);
        bn_finalize<<<1, 64>>>(st2, bn2g + i * 64, bn2b + i * 64, sc2, sh2, 64, invM);

        // h = relu(bn2(t2))
        bn_apply_relu<<<(NN * 16 + 255) / 256, 256>>>(t2, h, sc2, sh2, NN * 16);
    }

    pool_kernel<<<(NN * 32 + 255) / 256, 256>>>(h, batch, pool, cnt);
    div_kernel<<<(NGRAPH * HID + 255) / 256, 256>>>(pool, cnt, out);
}

// round 3
// speedup vs baseline: 1.0715x; 1.0715x over previous
#include <cuda_runtime.h>
#include <cuda_bf16.h>
#include <cstdint>

#define NN 100000
#define EE 1600000
#define NF 128
#define EF 32
#define HID 64
#define NLAYERS 3
#define NGRAPH 512

// ---------------- scratch buffers ----------------
__device__ float g_h[NN * HID];
__device__ float g_agg[NN * HID];
__device__ float g_t1[NN * 2 * HID];
__device__ float g_t2[NN * HID];
__device__ float g_st1[2 * 128];   // zeroed at load; bn_finalize re-zeroes after use
__device__ float g_st2[2 * 64];
__device__ float g_sc1[128], g_sh1[128];
__device__ float g_sc2[64],  g_sh2[64];
__device__ float g_pool[NGRAPH * HID];
__device__ float g_cnt[NGRAPH];
__device__ int   g_idx64;

// ---------------- f32x2 helpers ----------------
__device__ __forceinline__ unsigned long long f2pack(float x, float y) {
    unsigned long long r;
    asm("mov.b64 %0, {%1, %2};" : "=l"(r) : "f"(x), "f"(y));
    return r;
}
__device__ __forceinline__ void f2unpack(unsigned long long v, float& x, float& y) {
    asm("mov.b64 {%0, %1}, %2;" : "=f"(x), "=f"(y) : "l"(v));
}
__device__ __forceinline__ unsigned long long ffma2(unsigned long long a, unsigned long long b,
                                                    unsigned long long c) {
    unsigned long long d;
    asm("fma.rn.f32x2 %0, %1, %2, %3;" : "=l"(d) : "l"(a), "l"(b), "l"(c));
    return d;
}
__device__ __forceinline__ void red_add_v4(float* p, float4 v) {
    asm volatile("red.global.add.v4.f32 [%0], {%1,%2,%3,%4};"
                 :: "l"(p), "f"(v.x), "f"(v.y), "f"(v.z), "f"(v.w) : "memory");
}
__device__ __forceinline__ void red_add_v2(float* p, float2 v) {
    asm volatile("red.global.add.v2.f32 [%0], {%1,%2};"
                 :: "l"(p), "f"(v.x), "f"(v.y) : "memory");
}

// ---------------- dtype probe ----------------
__global__ void detect_kernel(const int* __restrict__ ei) {
    __shared__ int snz[8];
    int tid = threadIdx.x;           // 256 threads, 4 odd-words each
    int nz = 0;
#pragma unroll
    for (int l = 0; l < 4; ++l) nz |= ei[2 * (tid * 4 + l) + 1];
    nz = __reduce_or_sync(0xFFFFFFFF, nz);
    if ((tid & 31) == 0) snz[tid >> 5] = nz;
    __syncthreads();
    if (tid == 0) {
        int t = 0;
#pragma unroll
        for (int w = 0; w < 8; ++w) t |= snz[w];
        g_idx64 = (t == 0) ? 1 : 0;
    }
}

// ---------------- zero kernel ----------------
__global__ void zero_kernel(float4* __restrict__ p, int n4) {
    int i = blockIdx.x * blockDim.x + threadIdx.x;
    if (i < n4) p[i] = make_float4(0.f, 0.f, 0.f, 0.f);
}

// ---------------- tiled GEMM, 128-row blocks, 8 rows/thread ----------------
// AMODE 0: A0 ; AMODE 1: (1+eps)*A0+A1 ; AMODE 2: relu(A0*sc[k]+sh[k])
template <int K, int NC, int AMODE, bool STATS>
__global__ __launch_bounds__(256) void gemm_kernel(
    const float* __restrict__ A0, const float* __restrict__ A1,
    const float* __restrict__ B, const float* __restrict__ bias,
    float* __restrict__ C, float* __restrict__ stats,
    const float* __restrict__ sc, const float* __restrict__ sh,
    const float* __restrict__ epsp, int M)
{
    constexpr int BM = 128, BK = 32;
    constexpr int TN  = NC / 16;   // 4 or 8 cols/thread
    constexpr int TN2 = TN / 2;

    __shared__ float Ast[BK][BM + 4];   // transposed A tile
    __shared__ float Bs[BK][NC];
    __shared__ float scs[K], shs[K];
    __shared__ float ssum[NC], ssq[NC];

    const int tid = threadIdx.x;
    const int tx = tid & 15, ty = tid >> 4;   // 16 col-groups x 16 row-groups
    const int r0 = blockIdx.x * BM;

    float epsv = 0.f;
    if (AMODE == 1) epsv = 1.0f + *epsp;
    if (AMODE == 2) {
        for (int i = tid; i < K; i += 256) { scs[i] = sc[i]; shs[i] = sh[i]; }
    }
    if (STATS) {
        for (int i = tid; i < NC; i += 256) { ssum[i] = 0.f; ssq[i] = 0.f; }
    }
    if (AMODE == 2 || STATS) __syncthreads();

    unsigned long long acc[8][TN2];
#pragma unroll
    for (int i = 0; i < 8; ++i)
#pragma unroll
        for (int j = 0; j < TN2; ++j) acc[i][j] = 0ULL;

    for (int k0 = 0; k0 < K; k0 += BK) {
        // ---- A tile: 128x32 = 1024 float4, 4/thread; store transposed ----
#pragma unroll
        for (int l = 0; l < 4; ++l) {
            int idx = tid + l * 256;
            int row = idx >> 3;
            int q   = idx & 7;
            int grow = r0 + row;
            float4 v = make_float4(0.f, 0.f, 0.f, 0.f);
            if (grow < M) {
                int gk = k0 + q * 4;
                if (AMODE == 0) {
                    v = *(const float4*)&A0[(size_t)grow * K + gk];
                } else if (AMODE == 1) {
                    float4 hv = *(const float4*)&A0[(size_t)grow * K + gk];
                    float4 av = *(const float4*)&A1[(size_t)grow * K + gk];
                    v.x = fmaf(epsv, hv.x, av.x);
                    v.y = fmaf(epsv, hv.y, av.y);
                    v.z = fmaf(epsv, hv.z, av.z);
                    v.w = fmaf(epsv, hv.w, av.w);
                } else {
                    float4 tv = *(const float4*)&A0[(size_t)grow * K + gk];
                    v.x = fmaxf(fmaf(tv.x, scs[gk + 0], shs[gk + 0]), 0.f);
                    v.y = fmaxf(fmaf(tv.y, scs[gk + 1], shs[gk + 1]), 0.f);
                    v.z = fmaxf(fmaf(tv.z, scs[gk + 2], shs[gk + 2]), 0.f);
                    v.w = fmaxf(fmaf(tv.w, scs[gk + 3], shs[gk + 3]), 0.f);
                }
            }
            Ast[q * 4 + 0][row] = v.x;
            Ast[q * 4 + 1][row] = v.y;
            Ast[q * 4 + 2][row] = v.z;
            Ast[q * 4 + 3][row] = v.w;
        }
        // ---- B tile ----
        constexpr int BLD = (BK * NC / 4) / 256;
#pragma unroll
        for (int l = 0; l < BLD; ++l) {
            int idx = tid + l * 256;
            int kk = idx / (NC / 4);
            int c  = (idx % (NC / 4)) * 4;
            *(float4*)&Bs[kk][c] = *(const float4*)&B[(size_t)(k0 + kk) * NC + c];
        }
        __syncthreads();
#pragma unroll 4
        for (int kk = 0; kk < BK; ++kk) {
            float4 alo = *(const float4*)&Ast[kk][ty * 8];
            float4 ahi = *(const float4*)&Ast[kk][ty * 8 + 4];
            unsigned long long bp[TN2];
            {
                float4 bv0 = *(const float4*)&Bs[kk][tx * TN];
                bp[0] = f2pack(bv0.x, bv0.y);
                bp[1] = f2pack(bv0.z, bv0.w);
                if (TN == 8) {
                    float4 bv1 = *(const float4*)&Bs[kk][tx * TN + 4];
                    bp[TN2 > 2 ? 2 : 0] = f2pack(bv1.x, bv1.y);
                    bp[TN2 > 2 ? 3 : 0] = f2pack(bv1.z, bv1.w);
                }
            }
            float av[8] = {alo.x, alo.y, alo.z, alo.w, ahi.x, ahi.y, ahi.z, ahi.w};
#pragma unroll
            for (int i = 0; i < 8; ++i) {
                unsigned long long ap = f2pack(av[i], av[i]);
#pragma unroll
                for (int j = 0; j < TN2; ++j) acc[i][j] = ffma2(ap, bp[j], acc[i][j]);
            }
        }
        __syncthreads();
    }

    // ---- epilogue ----
    float bcol[TN];
#pragma unroll
    for (int j = 0; j < TN; ++j) bcol[j] = bias[tx * TN + j];

    float csum[TN], csq[TN];
#pragma unroll
    for (int j = 0; j < TN; ++j) { csum[j] = 0.f; csq[j] = 0.f; }

#pragma unroll
    for (int i = 0; i < 8; ++i) {
        int row = r0 + ty * 8 + i;
        if (row < M) {
            float o[TN];
#pragma unroll
            for (int j = 0; j < TN2; ++j) f2unpack(acc[i][j], o[2 * j], o[2 * j + 1]);
#pragma unroll
            for (int j = 0; j < TN; ++j) o[j] += bcol[j];
#pragma unroll
            for (int j4 = 0; j4 < TN; j4 += 4)
                *(float4*)&C[(size_t)row * NC + tx * TN + j4] =
                    make_float4(o[j4], o[j4 + 1], o[j4 + 2], o[j4 + 3]);
            if (STATS) {
#pragma unroll
                for (int j = 0; j < TN; ++j) { csum[j] += o[j]; csq[j] += o[j] * o[j]; }
            }
        }
    }
    if (STATS) {
#pragma unroll
        for (int j = 0; j < TN; ++j) {
            atomicAdd(&ssum[tx * TN + j], csum[j]);
            atomicAdd(&ssq[tx * TN + j], csq[j]);
        }
        __syncthreads();
        if (tid < NC) {
            atomicAdd(&stats[tid], ssum[tid]);
            atomicAdd(&stats[NC + tid], ssq[tid]);
        }
    }
}

// ---------------- BN finalize (re-zeroes stats for the next use) ----------------
__global__ void bn_finalize(float* __restrict__ stats, const float* __restrict__ g,
                            const float* __restrict__ b, float* __restrict__ sc,
                            float* __restrict__ sh, int NC, float invM)
{
    int i = threadIdx.x;
    if (i < NC) {
        float m = stats[i] * invM;
        float v = stats[NC + i] * invM - m * m;
        float rstd = rsqrtf(fmaxf(v, 0.f) + 1e-5f);
        float s = g[i] * rstd;
        sc[i] = s;
        sh[i] = b[i] - m * s;
        stats[i] = 0.f;
        stats[NC + i] = 0.f;
    }
}

// ---------------- BN2 apply + relu ----------------
__global__ void bn_apply_relu(const float* __restrict__ t, float* __restrict__ h,
                              const float* __restrict__ sc, const float* __restrict__ sh,
                              int total4)
{
    int i = blockIdx.x * 256 + threadIdx.x;
    if (i < total4) {
        float4 v = ((const float4*)t)[i];
        int c = (i & 15) * 4;
        float4 o;
        o.x = fmaxf(fmaf(v.x, sc[c + 0], sh[c + 0]), 0.f);
        o.y = fmaxf(fmaf(v.y, sc[c + 1], sh[c + 1]), 0.f);
        o.z = fmaxf(fmaf(v.z, sc[c + 2], sh[c + 2]), 0.f);
        o.w = fmaxf(fmaf(v.w, sc[c + 3], sh[c + 3]), 0.f);
        ((float4*)h)[i] = o;
    }
}

// ---------------- fused edge kernel (h gather prefetched before FMA loop) ----------------
__global__ __launch_bounds__(256) void edge_kernel(
    const float* __restrict__ attr, const int* __restrict__ eidx,
    const float* __restrict__ W, const float* __restrict__ eb,
    const float* __restrict__ h, float* __restrict__ agg)
{
    __shared__ float ws[32][64];
    __shared__ float att[128][36];
    __shared__ int   srcs[128], dsts[128];
    __shared__ float ebias[64];

    const int tid = threadIdx.x;
    const int e0 = blockIdx.x * 128;
    const int idx64 = g_idx64;

#pragma unroll
    for (int l = 0; l < 2; ++l) {
        int idx = tid + l * 256;
        ((float4*)&ws[0][0])[idx] = ((const float4*)W)[idx];
    }
    if (tid < 64) ebias[tid] = eb[tid];
    if (tid < 128) {
        if (idx64) {
            const long long* e64 = (const long long*)eidx;
            srcs[tid] = (int)e64[e0 + tid];
            dsts[tid] = (int)e64[EE + e0 + tid];
        } else {
            srcs[tid] = eidx[e0 + tid];
            dsts[tid] = eidx[EE + e0 + tid];
        }
    }
#pragma unroll
    for (int l = 0; l < 4; ++l) {
        int idx = tid + l * 256;
        int e = idx >> 3;
        int q = idx & 7;
        float4 v = *(const float4*)&attr[(size_t)(e0 + e) * EF + q * 4];
        *(float4*)&att[e][q * 4] = v;
    }
    __syncthreads();

    const int tx = tid & 7;    // col group tx*8
    const int ty = tid >> 3;   // edges ty*4 .. ty*4+3

    // ---- prefetch h[src] for all 4 edges BEFORE the FMA loop ----
    int sidx[4], didx[4];
    float4 hv0[4], hv1[4];
#pragma unroll
    for (int i = 0; i < 4; ++i) {
        sidx[i] = srcs[ty * 4 + i];
        didx[i] = dsts[ty * 4 + i];
        const float4* hp = (const float4*)&h[(size_t)sidx[i] * HID + tx * 8];
        hv0[i] = hp[0];
        hv1[i] = hp[1];
    }

    unsigned long long acc[4][4];
    unsigned long long bp0[4];
#pragma unroll
    for (int j = 0; j < 4; ++j)
        bp0[j] = f2pack(ebias[tx * 8 + 2 * j], ebias[tx * 8 + 2 * j + 1]);
#pragma unroll
    for (int i = 0; i < 4; ++i)
#pragma unroll
        for (int j = 0; j < 4; ++j) acc[i][j] = bp0[j];

#pragma unroll 8
    for (int kk = 0; kk < 32; ++kk) {
        const unsigned long long* wrow =
            reinterpret_cast<const unsigned long long*>(&ws[kk][tx * 8]);
        unsigned long long w0 = wrow[0], w1 = wrow[1], w2 = wrow[2], w3 = wrow[3];
#pragma unroll
        for (int i = 0; i < 4; ++i) {
            float a = att[ty * 4 + i][kk];
            unsigned long long ap = f2pack(a, a);
            acc[i][0] = ffma2(ap, w0, acc[i][0]);
            acc[i][1] = ffma2(ap, w1, acc[i][1]);
            acc[i][2] = ffma2(ap, w2, acc[i][2]);
            acc[i][3] = ffma2(ap, w3, acc[i][3]);
        }
    }

#pragma unroll
    for (int i = 0; i < 4; ++i) {
        float o[8];
        f2unpack(acc[i][0], o[0], o[1]);
        f2unpack(acc[i][1], o[2], o[3]);
        f2unpack(acc[i][2], o[4], o[5]);
        f2unpack(acc[i][3], o[6], o[7]);
        float4 m0 = make_float4(fmaxf(o[0] + hv0[i].x, 0.f), fmaxf(o[1] + hv0[i].y, 0.f),
                                fmaxf(o[2] + hv0[i].z, 0.f), fmaxf(o[3] + hv0[i].w, 0.f));
        float4 m1 = make_float4(fmaxf(o[4] + hv1[i].x, 0.f), fmaxf(o[5] + hv1[i].y, 0.f),
                                fmaxf(o[6] + hv1[i].z, 0.f), fmaxf(o[7] + hv1[i].w, 0.f));
        float* dp = &agg[(size_t)didx[i] * HID + tx * 8];
        red_add_v4(dp, m0);
        red_add_v4(dp + 4, m1);
    }
}

// ---------------- global mean pool ----------------
__global__ void pool_kernel(const float* __restrict__ h, const int* __restrict__ batch,
                            float* __restrict__ pool, float* __restrict__ cnt)
{
    int gid = blockIdx.x * 256 + threadIdx.x;
    if (gid >= NN * 32) return;
    int n = gid >> 5;
    int cp = gid & 31;
    int g = g_idx64 ? (int)((const long long*)batch)[n] : batch[n];
    float2 v = ((const float2*)h)[gid];
    red_add_v2(&pool[(size_t)g * HID + cp * 2], v);
    if (cp == 0) atomicAdd(&cnt[g], 1.0f);
}

__global__ void div_kernel(const float* __restrict__ pool, const float* __restrict__ cnt,
                           float* __restrict__ out)
{
    int i = blockIdx.x * 256 + threadIdx.x;
    if (i < NGRAPH * HID) {
        int g = i >> 6;
        out[i] = pool[i] / fmaxf(cnt[g], 1.0f);
    }
}

// ---------------- host launch ----------------
extern "C" void kernel_launch(void* const* d_in, const int* in_sizes, int n_in,
                              void* d_out, int out_size)
{
    const float* x     = (const float*)d_in[0];
    const int*   ei    = (const int*)d_in[1];
    const float* attr  = (const float*)d_in[2];
    const int*   batch = (const int*)d_in[3];
    const float* encW  = (const float*)d_in[4];
    const float* encb  = (const float*)d_in[5];
    const float* eps   = (const float*)d_in[6];
    const float* edgeW = (const float*)d_in[7];
    const float* edgeb = (const float*)d_in[8];
    const float* W1    = (const float*)d_in[9];
    const float* b1    = (const float*)d_in[10];
    const float* bn1g  = (const float*)d_in[11];
    const float* bn1b  = (const float*)d_in[12];
    const float* W2    = (const float*)d_in[13];
    const float* b2    = (const float*)d_in[14];
    const float* bn2g  = (const float*)d_in[15];
    const float* bn2b  = (const float*)d_in[16];
    float* out = (float*)d_out;

    float *h, *agg, *t1, *t2, *st1, *st2, *sc1, *sh1, *sc2, *sh2, *pool, *cnt;
    cudaGetSymbolAddress((void**)&h,   g_h);
    cudaGetSymbolAddress((void**)&agg, g_agg);
    cudaGetSymbolAddress((void**)&t1,  g_t1);
    cudaGetSymbolAddress((void**)&t2,  g_t2);
    cudaGetSymbolAddress((void**)&st1, g_st1);
    cudaGetSymbolAddress((void**)&st2, g_st2);
    cudaGetSymbolAddress((void**)&sc1, g_sc1);
    cudaGetSymbolAddress((void**)&sh1, g_sh1);
    cudaGetSymbolAddress((void**)&sc2, g_sc2);
    cudaGetSymbolAddress((void**)&sh2, g_sh2);
    cudaGetSymbolAddress((void**)&pool, g_pool);
    cudaGetSymbolAddress((void**)&cnt,  g_cnt);

    const int GB = (NN + 127) / 128;
    const float invM = 1.0f / (float)NN;

    detect_kernel<<<1, 256>>>(ei);

    zero_kernel<<<(NGRAPH * HID / 4 + 255) / 256, 256>>>((float4*)pool, NGRAPH * HID / 4);
    zero_kernel<<<1, 256>>>((float4*)cnt, NGRAPH / 4);

    gemm_kernel<128, 64, 0, false><<<GB, 256>>>(x, nullptr, encW, encb, h,
                                                nullptr, nullptr, nullptr, nullptr, NN);

    for (int i = 0; i < NLAYERS; ++i) {
        zero_kernel<<<(NN * 16 + 255) / 256, 256>>>((float4*)agg, NN * 16);

        edge_kernel<<<EE / 128, 256>>>(attr, ei, edgeW + (size_t)i * EF * HID,
                                       edgeb + i * HID, h, agg);

        gemm_kernel<64, 128, 1, true><<<GB, 256>>>(h, agg, W1 + (size_t)i * HID * 2 * HID,
                                                   b1 + i * 2 * HID, t1, st1,
                                                   nullptr, nullptr, eps + i, NN);
        bn_finalize<<<1, 128>>>(st1, bn1g + i * 128, bn1b + i * 128, sc1, sh1, 128, invM);

        gemm_kernel<128, 64, 2, true><<<GB, 256>>>(t1, nullptr, W2 + (size_t)i * 2 * HID * HID,
                                                   b2 + i * HID, t2, st2,
                                                   sc1, sh1, nullptr, NN);
        bn_finalize<<<1, 64>>>(st2, bn2g + i * 64, bn2b + i * 64, sc2, sh2, 64, invM);

        bn_apply_relu<<<(NN * 16 + 255) / 256, 256>>>(t2, h, sc2, sh2, NN * 16);
    }

    pool_kernel<<<(NN * 32 + 255) / 256, 256>>>(h, batch, pool, cnt);
    div_kernel<<<(NGRAPH * HID + 255) / 256, 256>>>(pool, cnt, out);
}